// round 6
// baseline (speedup 1.0000x reference)
#include <cuda_runtime.h>
#include <cstdint>
#include <cstddef>

// ---------------------------------------------------------------------------
// RankOneMoE, legacy tensor path (mma.sync.m16n8k8.tf32; harness PTX target is
// compute_103 without 'a' features, so no tcgen05).
//   gw[b,ek]  = (sum_s relu(x@gw1^T+b1g))[b,:]@gw2[ek,:]^T /512 + b2g[ek]
//   h         = relu([x | (x@SVH1^T)*gw] @ [W1^T ; U1] + b1m)
//   out       = [h | (h@SVH2^T)*gw] @ [W2^T ; U2] + b2m
// Operands pre-rounded to tf32 (rna), k-interleaved (LDS.128 frags).
// R6: register-software-pipelined mainloop (fa double-buffer, fb hoisted per
//     stage) to kill LDS->HMMA stalls; 4-stage pipe for BM64 kernels; fc2
//     reshaped for wave balance.
// ---------------------------------------------------------------------------

#define BQ   16
#define SQ   512
#define HQ   768
#define FQ   3072
#define EQ   8
#define EKQ  128
#define G1Q  256
#define NTOK (BQ*SQ)      // 8192
#define LAMBDA 0.2f
#define KSPLIT 4

// ---- scratch layout (floats) ----
#define OFF_XC    0                         // 8192*768
#define OFF_WG1   6291456                   // 256*768
#define OFF_SVH1  6488064                   // 128*768
#define OFF_W1    6586368                   // 3072*768
#define OFF_U1T   8945664                   // 3072*128
#define OFF_SVH2  9338880                   // 128*3072
#define OFF_W2    9732096                   // 768*3072
#define OFF_U2T   12091392                  // 768*128
#define OFF_G1    12189696                  // 8192*256
#define OFF_B1M   14292992                  // 3072
#define OFF_B2M   14296064                  // 768
#define OFF_T1S   14296832                  // 8192*128
#define OFF_T2S   15345408                  // 8192*128
#define OFF_H     16393984                  // 8192*3072
#define OFF_P8    41559808                  // 16*8*256
#define OFF_T2P   41592576                  // 4*8192*128
#define OFF_GWV   45786880                  // 16*128
#define SCRATCH_FLOATS 45788928

static __device__ __align__(256) float g_scratch[SCRATCH_FLOATS];

// ---------------------------- helpers --------------------------------------
__device__ __forceinline__ float tf32r(float a) {
    float r;
    asm("cvt.rna.tf32.f32 %0, %1;" : "=f"(r) : "f"(a));
    return r;
}
__device__ __forceinline__ uint32_t s2u(const void* p) {
    uint32_t a;
    asm("{ .reg .u64 t; cvta.to.shared.u64 t, %1; cvt.u32.u64 %0, t; }" : "=r"(a) : "l"(p));
    return a;
}
// interleave within 16-col group: c -> (c%4)*4 + c/4   (involution)
__device__ __forceinline__ int ilv16(int c) {
    return (c & ~15) | ((c & 3) << 2) | ((c >> 2) & 3);
}
__device__ __forceinline__ void mma8(float* c,
                                     uint32_t a0, uint32_t a1, uint32_t a2, uint32_t a3,
                                     uint32_t b0, uint32_t b1) {
    asm volatile(
        "mma.sync.aligned.m16n8k8.row.col.f32.tf32.tf32.f32 "
        "{%0,%1,%2,%3},{%4,%5,%6,%7},{%8,%9},{%0,%1,%2,%3};\n"
        : "+f"(c[0]), "+f"(c[1]), "+f"(c[2]), "+f"(c[3])
        : "r"(a0), "r"(a1), "r"(a2), "r"(a3), "r"(b0), "r"(b1));
}

// ---------------------------- pack kernels ---------------------------------
struct PackJobs {
    const float* src[6];
    float*       dst[6];
    int          ngroups[6];
};

__global__ void k_pack6(PackJobs J) {
    const int job = blockIdx.y;
    const int g = blockIdx.x * blockDim.x + threadIdx.x;
    if (g >= J.ngroups[job]) return;
    const float4* s = reinterpret_cast<const float4*>(J.src[job]) + (size_t)g * 4;
    float4 v0 = s[0], v1 = s[1], v2 = s[2], v3 = s[3];
    float4* d = reinterpret_cast<float4*>(J.dst[job]) + (size_t)g * 4;
    d[0] = make_float4(tf32r(v0.x), tf32r(v1.x), tf32r(v2.x), tf32r(v3.x));
    d[1] = make_float4(tf32r(v0.y), tf32r(v1.y), tf32r(v2.y), tf32r(v3.y));
    d[2] = make_float4(tf32r(v0.z), tf32r(v1.z), tf32r(v2.z), tf32r(v3.z));
    d[3] = make_float4(tf32r(v0.w), tf32r(v1.w), tf32r(v2.w), tf32r(v3.w));
}

__global__ void k_tr_ilv(const float* __restrict__ S_, float* __restrict__ Dst, int Ncols) {
    __shared__ float t[32][33];
    const int nx = blockIdx.x * 32, my = blockIdx.y * 32;
    const int x = threadIdx.x, y = threadIdx.y;
    #pragma unroll
    for (int i = 0; i < 32; i += 8)
        t[y + i][x] = S_[(size_t)(my + y + i) * Ncols + nx + x];
    __syncthreads();
    #pragma unroll
    for (int i = 0; i < 32; i += 8)
        Dst[(size_t)(nx + y + i) * 128 + ilv16(my + x)] = tf32r(t[x][y + i]);
}

__global__ void k_prep(const float* __restrict__ b1, const float* __restrict__ tb1,
                       const float* __restrict__ b2, const float* __restrict__ tb2,
                       float* __restrict__ b1m, float* __restrict__ b2m) {
    int i = blockIdx.x * blockDim.x + threadIdx.x;
    if (i < FQ) {
        float s = 0.f;
        #pragma unroll
        for (int e = 0; e < EQ; ++e) s += tb1[e * FQ + i];
        b1m[i] = b1[i] + LAMBDA * s;
    }
    if (i < HQ) {
        float s = 0.f;
        #pragma unroll
        for (int e = 0; e < EQ; ++e) s += tb2[e * HQ + i];
        b2m[i] = b2[i] + LAMBDA * s;
    }
}

// two-level mean reduction over S (level 1)
__global__ void k_sumG1b(const float* __restrict__ G1, float* __restrict__ P8) {
    int b = blockIdx.x, ch = blockIdx.y, g = threadIdx.x;      // 256 threads
    const float* p = G1 + ((size_t)b * SQ + ch * 64) * G1Q + g;
    float a = 0.f;
    #pragma unroll 8
    for (int s = 0; s < 64; ++s) a += p[(size_t)s * G1Q];
    P8[(b * 8 + ch) * G1Q + g] = a;
}

// t2 split-K reduce: sum 4 partials, scale by gw, round, interleave
__global__ void k_red(const float* __restrict__ t2p, const float* __restrict__ gwv,
                      float* __restrict__ t2s) {
    const int i = blockIdx.x * 256 + threadIdx.x;   // over 8192*128
    const int r = i >> 7, c = i & 127;
    float v = t2p[i];
    #pragma unroll
    for (int z = 1; z < KSPLIT; ++z) v += t2p[i + (size_t)z * NTOK * EKQ];
    t2s[((size_t)r << 7) + ilv16(c)] = tf32r(v * gwv[((r >> 9) << 7) + c]);
}

// ---------------------------------------------------------------------------
// Pipelined TF32 mma.sync GEMM on interleaved operands. BK=32 per stage,
// STAGES-deep cp.async, register-software-pipelined fragments:
//   per stage: hoist fb(half0)+fb(half1); fused 2*MT-step walk with
//   one-step-ahead fa double buffer -> one exposed LDS stall per stage.
//   EPI: 0=none, 1=relu, 2=scale by inline gw. SPLITK: z-slice of K1.
// ---------------------------------------------------------------------------
template<int BM, int BN, int WM, int WN, int STAGES, int EPI,
         bool HAS2, bool ROUND, bool HAS_BIAS, bool ILVOUT, bool INLINE_GW, bool SPLITK>
__global__ void __launch_bounds__(WM * WN * 32, 2)
k_mma(const float* __restrict__ A1, const float* __restrict__ B1, int K1,
      const float* __restrict__ A2, const float* __restrict__ B2, int K2,
      const float* __restrict__ bias,
      const float* __restrict__ P8, const float* __restrict__ w2g,
      const float* __restrict__ gb2, float* __restrict__ gwout,
      float* __restrict__ D, int N, int kspan)
{
    constexpr int THREADS = WM * WN * 32;
    constexpr int WTM = BM / WM, WTN = BN / WN;
    constexpr int MT = WTM / 16, NT = WTN / 8;
    constexpr int STGF = (BM + BN) * 32;          // floats per stage
    constexpr int AIT = (BM * 8) / THREADS;       // 16B chunks per thread (A)
    constexpr int BIT = (BN * 8) / THREADS;

    extern __shared__ float sm[];
    const uint32_t smb = s2u(sm);
    float* Ps  = sm + STAGES * STGF;              // [256] (INLINE_GW only)
    float* gws = Ps + G1Q;                        // [128]

    const int tid = threadIdx.x;
    const int wid = tid >> 5, lane = tid & 31;
    const int gid = lane >> 2, tig = lane & 3;
    const int wm = (wid / WN) * WTM;
    const int wn = (wid % WN) * WTN;
    const int bM = blockIdx.y * BM;
    const int bN = blockIdx.x * BN;
    const int kbase = SPLITK ? blockIdx.z * kspan : 0;
    const int T1S = SPLITK ? (kspan >> 5) : (K1 >> 5);
    const int TS  = T1S + (HAS2 ? (K2 >> 5) : 0);

    float* Dp = SPLITK ? (D + (size_t)blockIdx.z * NTOK * N) : D;

    float acc[MT][NT][4];
    #pragma unroll
    for (int mi = 0; mi < MT; ++mi)
        #pragma unroll
        for (int ni = 0; ni < NT; ++ni)
            #pragma unroll
            for (int j = 0; j < 4; ++j) acc[mi][ni][j] = 0.f;

    auto issue = [&](int jj) {
        const float* a; const float* b; int lda, ldb, k0;
        if (!HAS2 || jj < T1S) { a = A1; lda = K1; b = B1; ldb = K1; k0 = kbase + (jj << 5); }
        else                   { a = A2; lda = K2; b = B2; ldb = K2; k0 = (jj - T1S) << 5; }
        const uint32_t sA = smb + (uint32_t)((jj % STAGES) * STGF) * 4u;
        const uint32_t sB = sA + (uint32_t)BM * 128u;
        #pragma unroll
        for (int i = 0; i < AIT; ++i) {
            int idx = tid + i * THREADS;
            int r = idx >> 3, c = idx & 7, hf = c >> 2, cc = c & 3;
            const float* src = a + (size_t)(bM + r) * lda + k0 + hf * 16 + cc * 4;
            asm volatile("cp.async.cg.shared.global [%0], [%1], 16;\n"
                         :: "r"(sA + (uint32_t)(hf * BM * 64 + r * 64 + cc * 16)),
                            "l"(src) : "memory");
        }
        #pragma unroll
        for (int i = 0; i < BIT; ++i) {
            int idx = tid + i * THREADS;
            int r = idx >> 3, c = idx & 7, hf = c >> 2, cc = c & 3;
            const float* src = b + (size_t)(bN + r) * ldb + k0 + hf * 16 + cc * 4;
            asm volatile("cp.async.cg.shared.global [%0], [%1], 16;\n"
                         :: "r"(sB + (uint32_t)(hf * BN * 64 + r * 64 + cc * 16)),
                            "l"(src) : "memory");
        }
    };

    #pragma unroll
    for (int s = 0; s < STAGES - 1; ++s) {
        issue(s);
        asm volatile("cp.async.commit_group;\n" ::: "memory");
    }

    if (INLINE_GW) {
        // gw[b, c] = dot(P[b,:], w2[c,:]) / 512 + gb2[c];  b = bM>>9
        const int b = bM >> 9;
        float a = 0.f;
        #pragma unroll
        for (int ch = 0; ch < 8; ++ch) a += P8[(b * 8 + ch) * G1Q + tid];
        Ps[tid] = a;                                 // THREADS == 256 == G1Q
        __syncthreads();
        if (tid < EKQ) {
            const float* w = w2g + (size_t)tid * G1Q;
            float s = 0.f;
            #pragma unroll 8
            for (int g = 0; g < G1Q; ++g) s += w[g] * Ps[g];
            s = s * (1.0f / (float)SQ) + gb2[tid];
            gws[tid] = s;
            gwout[b * EKQ + tid] = s;                // duplicate writes OK
        }
    }

    for (int j = 0; j < TS; ++j) {
        asm volatile("cp.async.wait_group %0;\n" :: "n"(STAGES - 2) : "memory");
        __syncthreads();

        const float* sAst = sm + (j % STAGES) * STGF;
        const float* sA0 = sAst;
        const float* sA1 = sAst + BM * 16;
        const float* sB0 = sAst + 2 * BM * 16;
        const float* sB1 = sB0 + BN * 16;

        // hoist B fragments for both k16 halves
        float4 fb0[NT], fb1[NT];
        #pragma unroll
        for (int ni = 0; ni < NT; ++ni) {
            const int c = wn + ni * 8 + gid;
            fb0[ni] = *reinterpret_cast<const float4*>(sB0 + c * 16 + tig * 4);
            fb1[ni] = *reinterpret_cast<const float4*>(sB1 + c * 16 + tig * 4);
        }
        // prime fa double buffer (half0, mi=0)
        float4 fa[2][2];
        {
            const int r = wm + gid;
            fa[0][0] = *reinterpret_cast<const float4*>(sA0 + r * 16 + tig * 4);
            fa[0][1] = *reinterpret_cast<const float4*>(sA0 + (r + 8) * 16 + tig * 4);
        }

        if (j + STAGES - 1 < TS) issue(j + STAGES - 1);
        asm volatile("cp.async.commit_group;\n" ::: "memory");

        // fused walk: steps 0..MT-1 = half0, MT..2MT-1 = half1
        #pragma unroll
        for (int step = 0; step < 2 * MT; ++step) {
            const int h  = (step >= MT) ? 1 : 0;
            const int mi = h ? (step - MT) : step;
            const int buf = step & 1;
            if (step + 1 < 2 * MT) {                  // prefetch next fa
                const int ns  = step + 1;
                const int nh  = (ns >= MT) ? 1 : 0;
                const int nmi = nh ? (ns - MT) : ns;
                const float* base = nh ? sA1 : sA0;
                const int r = wm + nmi * 16 + gid;
                fa[buf ^ 1][0] = *reinterpret_cast<const float4*>(base + r * 16 + tig * 4);
                fa[buf ^ 1][1] = *reinterpret_cast<const float4*>(base + (r + 8) * 16 + tig * 4);
            }
            const float4 a0 = fa[buf][0], a1 = fa[buf][1];
            const float4* FB = h ? fb1 : fb0;
            #pragma unroll
            for (int ni = 0; ni < NT; ++ni)
                mma8(acc[mi][ni],
                     __float_as_uint(a0.x), __float_as_uint(a1.x),
                     __float_as_uint(a0.y), __float_as_uint(a1.y),
                     __float_as_uint(FB[ni].x), __float_as_uint(FB[ni].y));
            #pragma unroll
            for (int ni = 0; ni < NT; ++ni)
                mma8(acc[mi][ni],
                     __float_as_uint(a0.z), __float_as_uint(a1.z),
                     __float_as_uint(a0.w), __float_as_uint(a1.w),
                     __float_as_uint(FB[ni].z), __float_as_uint(FB[ni].w));
        }
    }

    // epilogue
    #pragma unroll
    for (int mi = 0; mi < MT; ++mi) {
        const int r0 = bM + wm + mi * 16 + gid;
        #pragma unroll
        for (int ni = 0; ni < NT; ++ni) {
            const int cl = wn + ni * 8 + tig * 2;
            const int c  = bN + cl;
            const float bb0 = HAS_BIAS ? bias[c] : 0.f;
            const float bb1 = HAS_BIAS ? bias[c + 1] : 0.f;
            #pragma unroll
            for (int h = 0; h < 2; ++h) {
                const int r = r0 + h * 8;
                float v0 = acc[mi][ni][2 * h + 0] + bb0;
                float v1 = acc[mi][ni][2 * h + 1] + bb1;
                if (EPI == 1) { v0 = fmaxf(v0, 0.f); v1 = fmaxf(v1, 0.f); }
                if (EPI == 2) { v0 *= gws[cl]; v1 *= gws[cl + 1]; }
                if (ROUND) { v0 = tf32r(v0); v1 = tf32r(v1); }
                if (ILVOUT) {
                    Dp[(size_t)r * N + ilv16(c)]     = v0;
                    Dp[(size_t)r * N + ilv16(c + 1)] = v1;
                } else {
                    *reinterpret_cast<float2*>(Dp + (size_t)r * N + c) = make_float2(v0, v1);
                }
            }
        }
    }
}

// ---------------------------------------------------------------------------
extern "C" void kernel_launch(void* const* d_in, const int* in_sizes, int n_in,
                              void* d_out, int out_size) {
    const float* x       = (const float*)d_in[0];
    const float* gate_w1 = (const float*)d_in[1];
    const float* gate_b1 = (const float*)d_in[2];
    const float* gate_w2 = (const float*)d_in[3];
    const float* gate_b2 = (const float*)d_in[4];
    const float* W1      = (const float*)d_in[5];
    const float* b1      = (const float*)d_in[6];
    const float* W2      = (const float*)d_in[7];
    const float* b2      = (const float*)d_in[8];
    const float* U1      = (const float*)d_in[9];
    const float* SVH1    = (const float*)d_in[10];
    const float* U2      = (const float*)d_in[11];
    const float* SVH2    = (const float*)d_in[12];
    const float* TB1     = (const float*)d_in[13];
    const float* TB2     = (const float*)d_in[14];
    float* out = (float*)d_out;

    float* S = nullptr;
    cudaGetSymbolAddress((void**)&S, g_scratch);
    float* xc    = S + OFF_XC;
    float* wg1c  = S + OFF_WG1;
    float* svh1c = S + OFF_SVH1;
    float* w1c   = S + OFF_W1;
    float* u1t   = S + OFF_U1T;
    float* svh2c = S + OFF_SVH2;
    float* w2c   = S + OFF_W2;
    float* u2t   = S + OFF_U2T;
    float* G1    = S + OFF_G1;
    float* b1m   = S + OFF_B1M;
    float* b2m   = S + OFF_B2M;
    float* t1s   = S + OFF_T1S;
    float* t2s   = S + OFF_T2S;
    float* hbuf  = S + OFF_H;
    float* P8    = S + OFF_P8;
    float* t2p   = S + OFF_T2P;
    float* gwv   = S + OFF_GWV;

    // router: BM64 BN128, 8 warps (2x4), warp 32x32, 4 stages
    auto kr = k_mma<64, 128, 2, 4, 4, 1, false, false, true, false, false, false>;
    // t1: BM64 BN128, 8 warps, inline gw, ILV out, 4 stages
    auto kt1 = k_mma<64, 128, 2, 4, 4, 2, false, true, false, true, true, false>;
    // t2 partial: split-K, raw out, 4 stages
    auto kt2 = k_mma<64, 128, 2, 4, 4, 0, false, false, false, false, false, true>;
    // fc1: BM128 BN128, 8 warps (2x4), warp 64x32, 3 stages
    auto k1 = k_mma<128, 128, 2, 4, 3, 1, true, true, true, true, false, false>;
    // fc2: BM64 BN128 (wave balance), warp 32x32, 4 stages
    auto k2 = k_mma<64, 128, 2, 4, 4, 0, true, false, true, false, false, false>;

    const int SM_RT = 4 * (64 + 128) * 32 * 4 + (G1Q + EKQ) * 4;   // 99840
    const int SM_F  = 3 * (128 + 128) * 32 * 4;                    // 98304
    cudaFuncSetAttribute((const void*)kr,  cudaFuncAttributeMaxDynamicSharedMemorySize, SM_RT);
    cudaFuncSetAttribute((const void*)kt1, cudaFuncAttributeMaxDynamicSharedMemorySize, SM_RT);
    cudaFuncSetAttribute((const void*)kt2, cudaFuncAttributeMaxDynamicSharedMemorySize, SM_RT);
    cudaFuncSetAttribute((const void*)k1,  cudaFuncAttributeMaxDynamicSharedMemorySize, SM_F);
    cudaFuncSetAttribute((const void*)k2,  cudaFuncAttributeMaxDynamicSharedMemorySize, SM_RT);

    // 0: all rounds+interleaves in one launch
    PackJobs J;
    J.src[0] = x;       J.dst[0] = xc;    J.ngroups[0] = NTOK * HQ / 16;
    J.src[1] = gate_w1; J.dst[1] = wg1c;  J.ngroups[1] = G1Q * HQ / 16;
    J.src[2] = SVH1;    J.dst[2] = svh1c; J.ngroups[2] = EKQ * HQ / 16;
    J.src[3] = W1;      J.dst[3] = w1c;   J.ngroups[3] = FQ * HQ / 16;
    J.src[4] = SVH2;    J.dst[4] = svh2c; J.ngroups[4] = EKQ * FQ / 16;
    J.src[5] = W2;      J.dst[5] = w2c;   J.ngroups[5] = HQ * FQ / 16;
    k_pack6<<<dim3((NTOK * HQ / 16 + 255) / 256, 6), 256>>>(J);

    // 1: router G1 = relu(x @ gate_w1^T + gate_b1)   [8192,256]
    kr<<<dim3(G1Q / 128, NTOK / 64), 256, SM_RT>>>(
        xc, wg1c, HQ, nullptr, nullptr, 0, gate_b1,
        nullptr, nullptr, nullptr, nullptr, G1, G1Q, 0);

    // 2: partial sums over S
    k_sumG1b<<<dim3(BQ, 8), 256>>>(G1, P8);

    // 3: t1s = round((x @ SVH1^T) * gw)  [8192,128] ILV  (gw inline)  << profiled
    kt1<<<dim3(1, NTOK / 64), 256, SM_RT>>>(
        xc, svh1c, HQ, nullptr, nullptr, 0, nullptr,
        P8, gate_w2, gate_b2, gwv, t1s, EKQ, 0);

    // 4,5: transposed low-rank factors
    k_tr_ilv<<<dim3(FQ / 32, 4), dim3(32, 8)>>>(U1, u1t, FQ);
    k_tr_ilv<<<dim3(HQ / 32, 4), dim3(32, 8)>>>(U2, u2t, HQ);

    // 6: merged biases
    k_prep<<<(FQ + 255) / 256, 256>>>(b1, TB1, b2, TB2, b1m, b2m);

    // 7: h = round(relu(x @ W1^T + t1s @ U1 + b1m))   [8192,3072] ILV
    k1<<<dim3(FQ / 128, NTOK / 128), 256, SM_F>>>(
        xc, w1c, HQ, t1s, u1t, EKQ, b1m,
        nullptr, nullptr, nullptr, nullptr, hbuf, FQ, 0);

    // 8: t2 partials = h @ SVH2^T, K split 4x768
    kt2<<<dim3(1, NTOK / 64, KSPLIT), 256, SM_RT>>>(
        hbuf, svh2c, FQ, nullptr, nullptr, 0, nullptr,
        nullptr, nullptr, nullptr, nullptr, t2p, EKQ, FQ / KSPLIT);

    // 9: t2s = round(sum_z t2p * gw)  ILV
    k_red<<<NTOK * EKQ / 256, 256>>>(t2p, gwv, t2s);

    // 10: out = h @ W2^T + t2s @ U2 + b2m   [8192,768]
    k2<<<dim3(HQ / 128, NTOK / 64), 256, SM_RT>>>(
        hbuf, w2c, FQ, t2s, u2t, EKQ, b2m,
        nullptr, nullptr, nullptr, nullptr, out, HQ, 0);
}

// round 7
// speedup vs baseline: 1.7798x; 1.7798x over previous
#include <cuda_runtime.h>
#include <cuda_fp16.h>
#include <cstdint>
#include <cstddef>

// ---------------------------------------------------------------------------
// RankOneMoE via fp16 mma.sync.m16n8k16 (fp32 accumulate). fp16 has the same
// 10-bit mantissa as tf32, so rna-rounded fp16 operands give tf32-equivalent
// accuracy at HALF the MMA instructions and HALF the smem bytes per flop.
//   gw[b,ek]  = (sum_s relu(x@gw1^T+b1g))[b,:]@gw2[ek,:]^T /512 + b2g[ek]
//   h         = relu([x | (x@SVH1^T)*gw] @ [W1^T ; U1] + b1m)
//   out       = [h | (h@SVH2^T)*gw] @ [W2^T ; U2] + b2m
// Operand layout: per 16-k group, halfs permuted [0,1,8,9,2,3,10,11,4,5,12,
// 13,6,7,14,15] so each thread's MMA fragment is one aligned LDS.64.
// Smem rows padded to 96B -> LDS.64 conflict-free (gid*96 mod 128 cycles
// {0,96,64,32}).
// ---------------------------------------------------------------------------

#define BQ   16
#define SQ   512
#define HQ   768
#define FQ   3072
#define EQ   8
#define EKQ  128
#define G1Q  256
#define NTOK (BQ*SQ)      // 8192
#define LAMBDA 0.2f
#define KSPLIT 4

// ---- scratch layout (float units; fp16 buffers use half the floats) ----
#define OFF_XC    0                         // 8192*768 h
#define OFF_WG1   3145728                   // 256*768 h
#define OFF_SVH1  3244032                   // 128*768 h
#define OFF_W1    3293184                   // 3072*768 h
#define OFF_U1T   4472832                   // 3072*128 h
#define OFF_SVH2  4669440                   // 128*3072 h
#define OFF_W2    4866048                   // 768*3072 h
#define OFF_U2T   6045696                   // 768*128 h
#define OFF_G1    6094848                   // 8192*256 f
#define OFF_T1S   8192000                   // 8192*128 h
#define OFF_T2S   8716288                   // 8192*128 h
#define OFF_H     9240576                   // 8192*3072 h
#define OFF_T2P   21823488                  // 4*8192*128 f
#define OFF_P8    26017792                  // 16*8*256 f
#define OFF_GWV   26050560                  // 16*128 f
#define OFF_B1M   26052608                  // 3072 f
#define OFF_B2M   26055680                  // 768 f
#define SCRATCH_FLOATS 26056448

static __device__ __align__(256) float g_scratch[SCRATCH_FLOATS];

// ---------------------------- helpers --------------------------------------
__device__ __forceinline__ uint32_t s2u(const void* p) {
    uint32_t a;
    asm("{ .reg .u64 t; cvta.to.shared.u64 t, %1; cvt.u32.u64 %0, t; }" : "=r"(a) : "l"(p));
    return a;
}
// position of original k (0..15) inside the permuted 16-group
__device__ __forceinline__ int ipos16(int k) {
    return (k & 1) + ((k >> 3) & 1) * 2 + (k & 6) * 2;
}
__device__ __forceinline__ void mma16(float* c,
                                      uint32_t a0, uint32_t a1, uint32_t a2, uint32_t a3,
                                      uint32_t b0, uint32_t b1) {
    asm volatile(
        "mma.sync.aligned.m16n8k16.row.col.f32.f16.f16.f32 "
        "{%0,%1,%2,%3},{%4,%5,%6,%7},{%8,%9},{%0,%1,%2,%3};\n"
        : "+f"(c[0]), "+f"(c[1]), "+f"(c[2]), "+f"(c[3])
        : "r"(a0), "r"(a1), "r"(a2), "r"(a3), "r"(b0), "r"(b1));
}

// ---------------------------- pack kernels ---------------------------------
struct PackJobs {
    const float* src[6];
    float*       dst[6];   // fp16 storage viewed as float words
    int          ngroups[6];
};

// fp32 -> fp16(rn) with per-16 k-pair permutation [0,1,8,9,2,3,10,11,...]
__global__ void k_pack6(PackJobs J) {
    const int job = blockIdx.y;
    const int g = blockIdx.x * blockDim.x + threadIdx.x;
    if (g >= J.ngroups[job]) return;
    const float4* s = reinterpret_cast<const float4*>(J.src[job]) + (size_t)g * 4;
    float4 v0 = s[0], v1 = s[1], v2 = s[2], v3 = s[3];   // k0-3, k4-7, k8-11, k12-15
    __half2 h[8];
    h[0] = __floats2half2_rn(v0.x, v0.y);   // k0,1
    h[1] = __floats2half2_rn(v2.x, v2.y);   // k8,9
    h[2] = __floats2half2_rn(v0.z, v0.w);   // k2,3
    h[3] = __floats2half2_rn(v2.z, v2.w);   // k10,11
    h[4] = __floats2half2_rn(v1.x, v1.y);   // k4,5
    h[5] = __floats2half2_rn(v3.x, v3.y);   // k12,13
    h[6] = __floats2half2_rn(v1.z, v1.w);   // k6,7
    h[7] = __floats2half2_rn(v3.z, v3.w);   // k14,15
    float4* d = reinterpret_cast<float4*>(reinterpret_cast<__half*>(J.dst[job]) + (size_t)g * 16);
    d[0] = *reinterpret_cast<float4*>(&h[0]);
    d[1] = *reinterpret_cast<float4*>(&h[4]);
}

// transpose src[128, Ncols] f32 -> dst[Ncols, 128] fp16 permuted
__global__ void k_tr_ilv(const float* __restrict__ S_, __half* __restrict__ Dst, int Ncols) {
    __shared__ float t[32][33];
    const int nx = blockIdx.x * 32, my = blockIdx.y * 32;
    const int x = threadIdx.x, y = threadIdx.y;
    #pragma unroll
    for (int i = 0; i < 32; i += 8)
        t[y + i][x] = S_[(size_t)(my + y + i) * Ncols + nx + x];
    __syncthreads();
    #pragma unroll
    for (int i = 0; i < 32; i += 8) {
        const int r = my + x;                 // original row (k of U^T)
        const int pos = (r & ~15) + ipos16(r & 15);
        Dst[(size_t)(nx + y + i) * 128 + pos] = __float2half_rn(t[x][y + i]);
    }
}

__global__ void k_prep(const float* __restrict__ b1, const float* __restrict__ tb1,
                       const float* __restrict__ b2, const float* __restrict__ tb2,
                       float* __restrict__ b1m, float* __restrict__ b2m) {
    int i = blockIdx.x * blockDim.x + threadIdx.x;
    if (i < FQ) {
        float s = 0.f;
        #pragma unroll
        for (int e = 0; e < EQ; ++e) s += tb1[e * FQ + i];
        b1m[i] = b1[i] + LAMBDA * s;
    }
    if (i < HQ) {
        float s = 0.f;
        #pragma unroll
        for (int e = 0; e < EQ; ++e) s += tb2[e * HQ + i];
        b2m[i] = b2[i] + LAMBDA * s;
    }
}

// two-level mean reduction over S (level 1)
__global__ void k_sumG1b(const float* __restrict__ G1, float* __restrict__ P8) {
    int b = blockIdx.x, ch = blockIdx.y, g = threadIdx.x;      // 256 threads
    const float* p = G1 + ((size_t)b * SQ + ch * 64) * G1Q + g;
    float a = 0.f;
    #pragma unroll 8
    for (int s = 0; s < 64; ++s) a += p[(size_t)s * G1Q];
    P8[(b * 8 + ch) * G1Q + g] = a;
}

// t2 split-K reduce: sum partials, scale by gw, convert to fp16 permuted
__global__ void k_red(const float* __restrict__ t2p, const float* __restrict__ gwv,
                      __half* __restrict__ t2s) {
    const int idx = blockIdx.x * 256 + threadIdx.x;   // over NTOK*64 pairs
    const int r = idx >> 6, c = (idx & 63) * 2;
    float v0 = t2p[(size_t)r * EKQ + c];
    float v1 = t2p[(size_t)r * EKQ + c + 1];
    #pragma unroll
    for (int z = 1; z < KSPLIT; ++z) {
        v0 += t2p[(size_t)z * NTOK * EKQ + (size_t)r * EKQ + c];
        v1 += t2p[(size_t)z * NTOK * EKQ + (size_t)r * EKQ + c + 1];
    }
    const int gb = (r >> 9) << 7;
    v0 *= gwv[gb + c]; v1 *= gwv[gb + c + 1];
    const int pos = (c & ~15) + ipos16(c & 15);       // pairs stay adjacent
    *reinterpret_cast<__half2*>(t2s + (size_t)r * EKQ + pos) = __floats2half2_rn(v0, v1);
}

// ---------------------------------------------------------------------------
// Pipelined fp16 mma.sync GEMM. BK=32 per stage (two 16-k groups), STAGES-deep
// cp.async. Smem rows: 32 halfs data (64B), stride 96B (conflict-free LDS.64).
//   D = epi( A1[M,K1] @ B1[N,K1]^T (+ A2[M,K2] @ B2[N,K2]^T) )
//   EPI: 0=none, 1=relu, 2=scale by inline gw. OUTH: fp16 permuted output.
// ---------------------------------------------------------------------------
template<int BM, int BN, int WM, int WN, int STAGES, int EPI,
         bool HAS2, bool HAS_BIAS, bool OUTH, bool INLINE_GW, bool SPLITK>
__global__ void __launch_bounds__(WM * WN * 32, 2)
k_mma(const __half* __restrict__ A1, const __half* __restrict__ B1, int K1,
      const __half* __restrict__ A2, const __half* __restrict__ B2, int K2,
      const float* __restrict__ bias,
      const float* __restrict__ P8, const float* __restrict__ w2g,
      const float* __restrict__ gb2, float* __restrict__ gwout,
      void* __restrict__ Dv, int N, int kspan)
{
    constexpr int THREADS = WM * WN * 32;
    constexpr int WTM = BM / WM, WTN = BN / WN;
    constexpr int MT = WTM / 16, NT = WTN / 8;
    constexpr int RB = 96;                        // padded row bytes (64B data)
    constexpr int STGB = (BM + BN) * RB;          // stage bytes
    constexpr int AIT = (BM * 4) / THREADS;       // 16B chunks per thread (A)
    constexpr int BIT = (BN * 4) / THREADS;

    extern __shared__ char sm[];
    const uint32_t smb = s2u(sm);
    float* Ps  = reinterpret_cast<float*>(sm + STAGES * STGB);   // [256]
    float* gws = Ps + G1Q;                                       // [128]

    const int tid = threadIdx.x;
    const int wid = tid >> 5, lane = tid & 31;
    const int gid = lane >> 2, tig = lane & 3;
    const int wm = (wid / WN) * WTM;
    const int wn = (wid % WN) * WTN;
    const int bM = blockIdx.y * BM;
    const int bN = blockIdx.x * BN;
    const int kbase = SPLITK ? blockIdx.z * kspan : 0;
    const int T1S = SPLITK ? (kspan >> 5) : (K1 >> 5);
    const int TS  = T1S + (HAS2 ? (K2 >> 5) : 0);

    float acc[MT][NT][4];
    #pragma unroll
    for (int mi = 0; mi < MT; ++mi)
        #pragma unroll
        for (int ni = 0; ni < NT; ++ni)
            #pragma unroll
            for (int j = 0; j < 4; ++j) acc[mi][ni][j] = 0.f;

    auto issue = [&](int jj) {
        const __half* a; const __half* b; int lda, ldb, k0;
        if (!HAS2 || jj < T1S) { a = A1; lda = K1; b = B1; ldb = K1; k0 = kbase + (jj << 5); }
        else                   { a = A2; lda = K2; b = B2; ldb = K2; k0 = (jj - T1S) << 5; }
        const uint32_t sA = smb + (uint32_t)((jj % STAGES) * STGB);
        const uint32_t sB = sA + (uint32_t)BM * RB;
        #pragma unroll
        for (int i = 0; i < AIT; ++i) {
            int idx = tid + i * THREADS; int r = idx >> 2, c = idx & 3;
            const __half* src = a + (size_t)(bM + r) * lda + k0 + c * 8;
            asm volatile("cp.async.cg.shared.global [%0], [%1], 16;\n"
                         :: "r"(sA + (uint32_t)(r * RB + c * 16)), "l"(src) : "memory");
        }
        #pragma unroll
        for (int i = 0; i < BIT; ++i) {
            int idx = tid + i * THREADS; int r = idx >> 2, c = idx & 3;
            const __half* src = b + (size_t)(bN + r) * ldb + k0 + c * 8;
            asm volatile("cp.async.cg.shared.global [%0], [%1], 16;\n"
                         :: "r"(sB + (uint32_t)(r * RB + c * 16)), "l"(src) : "memory");
        }
    };

    #pragma unroll
    for (int s = 0; s < STAGES - 1; ++s) {
        issue(s);
        asm volatile("cp.async.commit_group;\n" ::: "memory");
    }

    if (INLINE_GW) {
        // gw[b, c] = dot(P[b,:], w2[c,:]) / 512 + gb2[c];  b = bM>>9
        const int b = bM >> 9;
        float a = 0.f;
        #pragma unroll
        for (int ch = 0; ch < 8; ++ch) a += P8[(b * 8 + ch) * G1Q + tid];
        Ps[tid] = a;                                 // THREADS == 256 == G1Q
        __syncthreads();
        if (tid < EKQ) {
            const float* w = w2g + (size_t)tid * G1Q;
            float s = 0.f;
            #pragma unroll 8
            for (int g = 0; g < G1Q; ++g) s += w[g] * Ps[g];
            s = s * (1.0f / (float)SQ) + gb2[tid];
            gws[tid] = s;
            gwout[b * EKQ + tid] = s;                // duplicate writes OK
        }
    }

    for (int j = 0; j < TS; ++j) {
        asm volatile("cp.async.wait_group %0;\n" :: "n"(STAGES - 2) : "memory");
        __syncthreads();

        const char* sst = sm + (j % STAGES) * STGB;
        const char* sA = sst;
        const char* sB = sst + BM * RB;

        #pragma unroll
        for (int g = 0; g < 2; ++g) {
            uint2 fb[NT];
            #pragma unroll
            for (int ni = 0; ni < NT; ++ni)
                fb[ni] = *reinterpret_cast<const uint2*>(
                    sB + (wn + ni * 8 + gid) * RB + g * 32 + tig * 8);

            if (g == 0) {
                if (j + STAGES - 1 < TS) issue(j + STAGES - 1);
                asm volatile("cp.async.commit_group;\n" ::: "memory");
            }

            #pragma unroll
            for (int mi = 0; mi < MT; ++mi) {
                const char* ra = sA + (wm + mi * 16 + gid) * RB + g * 32 + tig * 8;
                const uint2 fa0 = *reinterpret_cast<const uint2*>(ra);
                const uint2 fa1 = *reinterpret_cast<const uint2*>(ra + 8 * RB);
                #pragma unroll
                for (int ni = 0; ni < NT; ++ni)
                    mma16(acc[mi][ni], fa0.x, fa1.x, fa0.y, fa1.y,
                          fb[ni].x, fb[ni].y);
            }
        }
    }

    // epilogue
    float* Df = reinterpret_cast<float*>(Dv)
              + (SPLITK ? (size_t)blockIdx.z * NTOK * N : 0);
    __half* Dh = reinterpret_cast<__half*>(Dv);
    #pragma unroll
    for (int mi = 0; mi < MT; ++mi) {
        const int r0 = bM + wm + mi * 16 + gid;
        #pragma unroll
        for (int ni = 0; ni < NT; ++ni) {
            const int cl = wn + ni * 8 + tig * 2;
            const int c  = bN + cl;
            const float bb0 = HAS_BIAS ? bias[c] : 0.f;
            const float bb1 = HAS_BIAS ? bias[c + 1] : 0.f;
            #pragma unroll
            for (int h = 0; h < 2; ++h) {
                const int r = r0 + h * 8;
                float v0 = acc[mi][ni][2 * h + 0] + bb0;
                float v1 = acc[mi][ni][2 * h + 1] + bb1;
                if (EPI == 1) { v0 = fmaxf(v0, 0.f); v1 = fmaxf(v1, 0.f); }
                if (EPI == 2) { v0 *= gws[bN + cl]; v1 *= gws[bN + cl + 1]; }
                if (OUTH) {
                    const int pos = (c & ~15) + ipos16(c & 15);
                    *reinterpret_cast<__half2*>(Dh + (size_t)r * N + pos) =
                        __floats2half2_rn(v0, v1);
                } else {
                    *reinterpret_cast<float2*>(Df + (size_t)r * N + c) = make_float2(v0, v1);
                }
            }
        }
    }
}

// ---------------------------------------------------------------------------
extern "C" void kernel_launch(void* const* d_in, const int* in_sizes, int n_in,
                              void* d_out, int out_size) {
    const float* x       = (const float*)d_in[0];
    const float* gate_w1 = (const float*)d_in[1];
    const float* gate_b1 = (const float*)d_in[2];
    const float* gate_w2 = (const float*)d_in[3];
    const float* gate_b2 = (const float*)d_in[4];
    const float* W1      = (const float*)d_in[5];
    const float* b1      = (const float*)d_in[6];
    const float* W2      = (const float*)d_in[7];
    const float* b2      = (const float*)d_in[8];
    const float* U1      = (const float*)d_in[9];
    const float* SVH1    = (const float*)d_in[10];
    const float* U2      = (const float*)d_in[11];
    const float* SVH2    = (const float*)d_in[12];
    const float* TB1     = (const float*)d_in[13];
    const float* TB2     = (const float*)d_in[14];
    float* out = (float*)d_out;

    float* S = nullptr;
    cudaGetSymbolAddress((void**)&S, g_scratch);
    __half* xc    = (__half*)(S + OFF_XC);
    __half* wg1c  = (__half*)(S + OFF_WG1);
    __half* svh1c = (__half*)(S + OFF_SVH1);
    __half* w1c   = (__half*)(S + OFF_W1);
    __half* u1t   = (__half*)(S + OFF_U1T);
    __half* svh2c = (__half*)(S + OFF_SVH2);
    __half* w2c   = (__half*)(S + OFF_W2);
    __half* u2t   = (__half*)(S + OFF_U2T);
    __half* t1s   = (__half*)(S + OFF_T1S);
    __half* t2s   = (__half*)(S + OFF_T2S);
    __half* hbuf  = (__half*)(S + OFF_H);
    float* G1    = S + OFF_G1;
    float* t2p   = S + OFF_T2P;
    float* P8    = S + OFF_P8;
    float* gwv   = S + OFF_GWV;
    float* b1m   = S + OFF_B1M;
    float* b2m   = S + OFF_B2M;

    // router: BM64 BN128, 8 warps (2x4), warp 32x32, 4 stages, fp32 out
    auto kr = k_mma<64, 128, 2, 4, 4, 1, false, true, false, false, false>;
    // t1: BM64 BN64, 8 warps, inline gw, fp16 ILV out, 4 stages
    auto kt1 = k_mma<64, 64, 2, 4, 4, 2, false, false, true, true, false>;
    // t2 partial: split-K, fp32 raw out, 4 stages
    auto kt2 = k_mma<64, 128, 2, 4, 4, 0, false, false, false, false, true>;
    // fc1: BM128 BN128, 8 warps (2x4), warp 64x32, 3 stages, fp16 ILV out
    auto k1 = k_mma<128, 128, 2, 4, 3, 1, true, true, true, false, false>;
    // fc2: BM128 BN128, 3 stages, fp32 out
    auto k2 = k_mma<128, 128, 2, 4, 3, 0, true, true, false, false, false>;

    const int SM_R  = 4 * (64 + 128) * 96;                    // 73728
    const int SM_T1 = 4 * (64 + 64) * 96 + (G1Q + EKQ) * 4;   // 50688
    const int SM_T2 = 4 * (64 + 128) * 96;                    // 73728
    const int SM_F  = 3 * (128 + 128) * 96;                   // 73728
    cudaFuncSetAttribute((const void*)kr,  cudaFuncAttributeMaxDynamicSharedMemorySize, SM_R);
    cudaFuncSetAttribute((const void*)kt1, cudaFuncAttributeMaxDynamicSharedMemorySize, SM_T1);
    cudaFuncSetAttribute((const void*)kt2, cudaFuncAttributeMaxDynamicSharedMemorySize, SM_T2);
    cudaFuncSetAttribute((const void*)k1,  cudaFuncAttributeMaxDynamicSharedMemorySize, SM_F);
    cudaFuncSetAttribute((const void*)k2,  cudaFuncAttributeMaxDynamicSharedMemorySize, SM_F);

    // 0: all fp32->fp16(rn) packs with k-permutation, one launch
    PackJobs J;
    J.src[0] = x;       J.dst[0] = (float*)xc;    J.ngroups[0] = NTOK * HQ / 16;
    J.src[1] = gate_w1; J.dst[1] = (float*)wg1c;  J.ngroups[1] = G1Q * HQ / 16;
    J.src[2] = SVH1;    J.dst[2] = (float*)svh1c; J.ngroups[2] = EKQ * HQ / 16;
    J.src[3] = W1;      J.dst[3] = (float*)w1c;   J.ngroups[3] = FQ * HQ / 16;
    J.src[4] = SVH2;    J.dst[4] = (float*)svh2c; J.ngroups[4] = EKQ * FQ / 16;
    J.src[5] = W2;      J.dst[5] = (float*)w2c;   J.ngroups[5] = HQ * FQ / 16;
    k_pack6<<<dim3((NTOK * HQ / 16 + 255) / 256, 6), 256>>>(J);

    // 1: router G1 = relu(x @ gate_w1^T + gate_b1)   [8192,256] fp32
    kr<<<dim3(G1Q / 128, NTOK / 64), 256, SM_R>>>(
        xc, wg1c, HQ, nullptr, nullptr, 0, gate_b1,
        nullptr, nullptr, nullptr, nullptr, G1, G1Q, 0);

    // 2: partial sums over S
    k_sumG1b<<<dim3(BQ, 8), 256>>>(G1, P8);

    // 3: t1s = fp16((x @ SVH1^T) * gw)  [8192,128]  (gw inline, persisted)
    kt1<<<dim3(EKQ / 64, NTOK / 64), 256, SM_T1>>>(
        xc, svh1c, HQ, nullptr, nullptr, 0, nullptr,
        P8, gate_w2, gate_b2, gwv, t1s, EKQ, 0);

    // 4,5: transposed low-rank factors -> fp16 permuted
    k_tr_ilv<<<dim3(FQ / 32, 4), dim3(32, 8)>>>(U1, u1t, FQ);
    k_tr_ilv<<<dim3(HQ / 32, 4), dim3(32, 8)>>>(U2, u2t, HQ);

    // 6: merged biases (fp32)
    k_prep<<<(FQ + 255) / 256, 256>>>(b1, TB1, b2, TB2, b1m, b2m);

    // 7: h = fp16(relu(x @ W1^T + t1s @ U1 + b1m))   [8192,3072]
    k1<<<dim3(FQ / 128, NTOK / 128), 256, SM_F>>>(
        xc, w1c, HQ, t1s, u1t, EKQ, b1m,
        nullptr, nullptr, nullptr, nullptr, hbuf, FQ, 0);

    // 8: t2 partials = h @ SVH2^T, K split 4x768, fp32
    kt2<<<dim3(1, NTOK / 64, KSPLIT), 256, SM_T2>>>(
        hbuf, svh2c, FQ, nullptr, nullptr, 0, nullptr,
        nullptr, nullptr, nullptr, nullptr, t2p, EKQ, FQ / KSPLIT);

    // 9: t2s = fp16(sum_z t2p * gw)
    k_red<<<NTOK * 64 / 256, 256>>>(t2p, gwv, t2s);

    // 10: out = h @ W2^T + t2s @ U2 + b2m   [8192,768] fp32
    k2<<<dim3(HQ / 128, NTOK / 128), 256, SM_F>>>(
        hbuf, w2c, FQ, t2s, u2t, EKQ, b2m,
        nullptr, nullptr, nullptr, nullptr, out, HQ, 0);
}

// round 8
// speedup vs baseline: 1.8628x; 1.0466x over previous
#include <cuda_runtime.h>
#include <cuda_fp16.h>
#include <cstdint>
#include <cstddef>

// ---------------------------------------------------------------------------
// RankOneMoE via fp16 mma.sync.m16n8k16 (fp32 accumulate). fp16 mantissa ==
// tf32 mantissa, so rn-rounded fp16 operands give tf32-grade accuracy at half
// the MMA instructions and half the smem bytes.
//   gw[b,ek]  = (sum_s relu(x@gw1^T+b1g))[b,:]@gw2[ek,:]^T /512 + b2g[ek]
//   h         = relu([x | (x@SVH1^T)*gw] @ [W1^T ; U1] + b1m)
//   out       = [h | (h@SVH2^T)*gw] @ [W2^T ; U2] + b2m
// Per-16 k-pair permutation [0,1,8,9,2,3,10,11,...] -> fragment = 1 LDS.64.
// Rows padded to 96B (conflict-free LDS.64). R8: t1/t2 both split-K with a
// fused reduce (gw scale + fp16 + permute); gw via tiny dedicated kernel;
// fc pipelines deepened to 4 stages.
// ---------------------------------------------------------------------------

#define BQ   16
#define SQ   512
#define HQ   768
#define FQ   3072
#define EQ   8
#define EKQ  128
#define G1Q  256
#define NTOK (BQ*SQ)      // 8192
#define LAMBDA 0.2f

// ---- scratch layout (float units; fp16 buffers use half the floats) ----
#define OFF_XC    0                         // 8192*768 h
#define OFF_WG1   3145728                   // 256*768 h
#define OFF_SVH1  3244032                   // 128*768 h
#define OFF_W1    3293184                   // 3072*768 h
#define OFF_U1T   4472832                   // 3072*128 h
#define OFF_SVH2  4669440                   // 128*3072 h
#define OFF_W2    4866048                   // 768*3072 h
#define OFF_U2T   6045696                   // 768*128 h
#define OFF_G1    6094848                   // 8192*256 f
#define OFF_T1S   8192000                   // 8192*128 h
#define OFF_T2S   8716288                   // 8192*128 h
#define OFF_H     9240576                   // 8192*3072 h
#define OFF_T2P   21823488                  // 4*8192*128 f
#define OFF_P8    26017792                  // 16*8*256 f
#define OFF_GWV   26050560                  // 16*128 f
#define OFF_B1M   26052608                  // 3072 f
#define OFF_B2M   26055680                  // 768 f
#define OFF_T1P   26056448                  // 2*8192*128 f
#define SCRATCH_FLOATS 28153600

static __device__ __align__(256) float g_scratch[SCRATCH_FLOATS];

// ---------------------------- helpers --------------------------------------
__device__ __forceinline__ uint32_t s2u(const void* p) {
    uint32_t a;
    asm("{ .reg .u64 t; cvta.to.shared.u64 t, %1; cvt.u32.u64 %0, t; }" : "=r"(a) : "l"(p));
    return a;
}
// position of original k (0..15) inside the permuted 16-group
__device__ __forceinline__ int ipos16(int k) {
    return (k & 1) + ((k >> 3) & 1) * 2 + (k & 6) * 2;
}
__device__ __forceinline__ void mma16(float* c,
                                      uint32_t a0, uint32_t a1, uint32_t a2, uint32_t a3,
                                      uint32_t b0, uint32_t b1) {
    asm volatile(
        "mma.sync.aligned.m16n8k16.row.col.f32.f16.f16.f32 "
        "{%0,%1,%2,%3},{%4,%5,%6,%7},{%8,%9},{%0,%1,%2,%3};\n"
        : "+f"(c[0]), "+f"(c[1]), "+f"(c[2]), "+f"(c[3])
        : "r"(a0), "r"(a1), "r"(a2), "r"(a3), "r"(b0), "r"(b1));
}

// ---------------------------- pack kernels ---------------------------------
struct PackJobs {
    const float* src[6];
    float*       dst[6];   // fp16 storage viewed as float words
    int          ngroups[6];
};

// fp32 -> fp16(rn) with per-16 k-pair permutation [0,1,8,9,2,3,10,11,...]
__global__ void k_pack6(PackJobs J) {
    const int job = blockIdx.y;
    const int g = blockIdx.x * blockDim.x + threadIdx.x;
    if (g >= J.ngroups[job]) return;
    const float4* s = reinterpret_cast<const float4*>(J.src[job]) + (size_t)g * 4;
    float4 v0 = s[0], v1 = s[1], v2 = s[2], v3 = s[3];   // k0-3, k4-7, k8-11, k12-15
    __half2 h[8];
    h[0] = __floats2half2_rn(v0.x, v0.y);   // k0,1
    h[1] = __floats2half2_rn(v2.x, v2.y);   // k8,9
    h[2] = __floats2half2_rn(v0.z, v0.w);   // k2,3
    h[3] = __floats2half2_rn(v2.z, v2.w);   // k10,11
    h[4] = __floats2half2_rn(v1.x, v1.y);   // k4,5
    h[5] = __floats2half2_rn(v3.x, v3.y);   // k12,13
    h[6] = __floats2half2_rn(v1.z, v1.w);   // k6,7
    h[7] = __floats2half2_rn(v3.z, v3.w);   // k14,15
    float4* d = reinterpret_cast<float4*>(reinterpret_cast<__half*>(J.dst[job]) + (size_t)g * 16);
    d[0] = *reinterpret_cast<float4*>(&h[0]);
    d[1] = *reinterpret_cast<float4*>(&h[4]);
}

// transpose src[128, Ncols] f32 -> dst[Ncols, 128] fp16 permuted
__global__ void k_tr_ilv(const float* __restrict__ S_, __half* __restrict__ Dst, int Ncols) {
    __shared__ float t[32][33];
    const int nx = blockIdx.x * 32, my = blockIdx.y * 32;
    const int x = threadIdx.x, y = threadIdx.y;
    #pragma unroll
    for (int i = 0; i < 32; i += 8)
        t[y + i][x] = S_[(size_t)(my + y + i) * Ncols + nx + x];
    __syncthreads();
    #pragma unroll
    for (int i = 0; i < 32; i += 8) {
        const int r = my + x;                 // original row (k of U^T)
        const int pos = (r & ~15) + ipos16(r & 15);
        Dst[(size_t)(nx + y + i) * 128 + pos] = __float2half_rn(t[x][y + i]);
    }
}

__global__ void k_prep(const float* __restrict__ b1, const float* __restrict__ tb1,
                       const float* __restrict__ b2, const float* __restrict__ tb2,
                       float* __restrict__ b1m, float* __restrict__ b2m) {
    int i = blockIdx.x * blockDim.x + threadIdx.x;
    if (i < FQ) {
        float s = 0.f;
        #pragma unroll
        for (int e = 0; e < EQ; ++e) s += tb1[e * FQ + i];
        b1m[i] = b1[i] + LAMBDA * s;
    }
    if (i < HQ) {
        float s = 0.f;
        #pragma unroll
        for (int e = 0; e < EQ; ++e) s += tb2[e * HQ + i];
        b2m[i] = b2[i] + LAMBDA * s;
    }
}

// two-level mean reduction over S (level 1)
__global__ void k_sumG1b(const float* __restrict__ G1, float* __restrict__ P8) {
    int b = blockIdx.x, ch = blockIdx.y, g = threadIdx.x;      // 256 threads
    const float* p = G1 + ((size_t)b * SQ + ch * 64) * G1Q + g;
    float a = 0.f;
    #pragma unroll 8
    for (int s = 0; s < 64; ++s) a += p[(size_t)s * G1Q];
    P8[(b * 8 + ch) * G1Q + g] = a;
}

// gw[b,ek] = dot(P[b,:], w2[ek,:]) / 512 + gb2[ek]
__global__ void k_gwfin(const float* __restrict__ P8, const float* __restrict__ w2,
                        const float* __restrict__ gb2, float* __restrict__ gw) {
    __shared__ float Ps[G1Q];
    int b = blockIdx.x, t = threadIdx.x;   // 128 threads
    #pragma unroll
    for (int half = 0; half < 2; ++half) {
        int col = t + half * 128;
        float a = 0.f;
        #pragma unroll
        for (int ch = 0; ch < 8; ++ch) a += P8[(b * 8 + ch) * G1Q + col];
        Ps[col] = a;
    }
    __syncthreads();
    const float* w = w2 + (size_t)t * G1Q;
    float a = 0.f;
    #pragma unroll 8
    for (int g = 0; g < G1Q; ++g) a += w[g] * Ps[g];
    gw[b * EKQ + t] = a * (1.0f / (float)SQ) + gb2[t];
}

// split-K reduce: sum KS partials, scale by gw, convert to fp16 permuted
template<int KS>
__global__ void k_red(const float* __restrict__ tp, const float* __restrict__ gwv,
                      __half* __restrict__ ts) {
    const int idx = blockIdx.x * 256 + threadIdx.x;   // over NTOK*64 pairs
    const int r = idx >> 6, c = (idx & 63) * 2;
    float v0 = tp[(size_t)r * EKQ + c];
    float v1 = tp[(size_t)r * EKQ + c + 1];
    #pragma unroll
    for (int z = 1; z < KS; ++z) {
        v0 += tp[(size_t)z * NTOK * EKQ + (size_t)r * EKQ + c];
        v1 += tp[(size_t)z * NTOK * EKQ + (size_t)r * EKQ + c + 1];
    }
    const int gb = (r >> 9) << 7;
    v0 *= gwv[gb + c]; v1 *= gwv[gb + c + 1];
    const int pos = (c & ~15) + ipos16(c & 15);       // pairs stay adjacent
    *reinterpret_cast<__half2*>(ts + (size_t)r * EKQ + pos) = __floats2half2_rn(v0, v1);
}

// ---------------------------------------------------------------------------
// Pipelined fp16 mma.sync GEMM. BK=32 per stage (two 16-k groups), STAGES-deep
// cp.async. Smem rows: 32 halfs data (64B), stride 96B (conflict-free LDS.64).
//   D = epi( A1[M,K1] @ B1[N,K1]^T (+ A2[M,K2] @ B2[N,K2]^T) )
//   EPI: 0=none, 1=relu. OUTH: fp16 permuted output.
//   SPLITK: blockIdx.z picks a kspan window of K1; D offset by z*NTOK*N.
// ---------------------------------------------------------------------------
template<int BM, int BN, int WM, int WN, int STAGES, int EPI,
         bool HAS2, bool HAS_BIAS, bool OUTH, bool SPLITK>
__global__ void __launch_bounds__(WM * WN * 32, 2)
k_mma(const __half* __restrict__ A1, const __half* __restrict__ B1, int K1,
      const __half* __restrict__ A2, const __half* __restrict__ B2, int K2,
      const float* __restrict__ bias,
      void* __restrict__ Dv, int N, int kspan)
{
    constexpr int THREADS = WM * WN * 32;
    constexpr int WTM = BM / WM, WTN = BN / WN;
    constexpr int MT = WTM / 16, NT = WTN / 8;
    constexpr int RB = 96;                        // padded row bytes (64B data)
    constexpr int STGB = (BM + BN) * RB;          // stage bytes
    constexpr int AIT = (BM * 4) / THREADS;       // 16B chunks per thread (A)
    constexpr int BIT = (BN * 4) / THREADS;

    extern __shared__ char sm[];
    const uint32_t smb = s2u(sm);

    const int tid = threadIdx.x;
    const int wid = tid >> 5, lane = tid & 31;
    const int gid = lane >> 2, tig = lane & 3;
    const int wm = (wid / WN) * WTM;
    const int wn = (wid % WN) * WTN;
    const int bM = blockIdx.y * BM;
    const int bN = blockIdx.x * BN;
    const int kbase = SPLITK ? blockIdx.z * kspan : 0;
    const int T1S = SPLITK ? (kspan >> 5) : (K1 >> 5);
    const int TS  = T1S + (HAS2 ? (K2 >> 5) : 0);

    float acc[MT][NT][4];
    #pragma unroll
    for (int mi = 0; mi < MT; ++mi)
        #pragma unroll
        for (int ni = 0; ni < NT; ++ni)
            #pragma unroll
            for (int j = 0; j < 4; ++j) acc[mi][ni][j] = 0.f;

    auto issue = [&](int jj) {
        const __half* a; const __half* b; int lda, ldb, k0;
        if (!HAS2 || jj < T1S) { a = A1; lda = K1; b = B1; ldb = K1; k0 = kbase + (jj << 5); }
        else                   { a = A2; lda = K2; b = B2; ldb = K2; k0 = (jj - T1S) << 5; }
        const uint32_t sA = smb + (uint32_t)((jj % STAGES) * STGB);
        const uint32_t sB = sA + (uint32_t)BM * RB;
        #pragma unroll
        for (int i = 0; i < AIT; ++i) {
            int idx = tid + i * THREADS; int r = idx >> 2, c = idx & 3;
            const __half* src = a + (size_t)(bM + r) * lda + k0 + c * 8;
            asm volatile("cp.async.cg.shared.global [%0], [%1], 16;\n"
                         :: "r"(sA + (uint32_t)(r * RB + c * 16)), "l"(src) : "memory");
        }
        #pragma unroll
        for (int i = 0; i < BIT; ++i) {
            int idx = tid + i * THREADS; int r = idx >> 2, c = idx & 3;
            const __half* src = b + (size_t)(bN + r) * ldb + k0 + c * 8;
            asm volatile("cp.async.cg.shared.global [%0], [%1], 16;\n"
                         :: "r"(sB + (uint32_t)(r * RB + c * 16)), "l"(src) : "memory");
        }
    };

    #pragma unroll
    for (int s = 0; s < STAGES - 1; ++s) {
        issue(s);
        asm volatile("cp.async.commit_group;\n" ::: "memory");
    }

    for (int j = 0; j < TS; ++j) {
        asm volatile("cp.async.wait_group %0;\n" :: "n"(STAGES - 2) : "memory");
        __syncthreads();

        const char* sst = sm + (j % STAGES) * STGB;
        const char* sA = sst;
        const char* sB = sst + BM * RB;

        #pragma unroll
        for (int g = 0; g < 2; ++g) {
            uint2 fb[NT];
            #pragma unroll
            for (int ni = 0; ni < NT; ++ni)
                fb[ni] = *reinterpret_cast<const uint2*>(
                    sB + (wn + ni * 8 + gid) * RB + g * 32 + tig * 8);

            if (g == 0) {
                if (j + STAGES - 1 < TS) issue(j + STAGES - 1);
                asm volatile("cp.async.commit_group;\n" ::: "memory");
            }

            #pragma unroll
            for (int mi = 0; mi < MT; ++mi) {
                const char* ra = sA + (wm + mi * 16 + gid) * RB + g * 32 + tig * 8;
                const uint2 fa0 = *reinterpret_cast<const uint2*>(ra);
                const uint2 fa1 = *reinterpret_cast<const uint2*>(ra + 8 * RB);
                #pragma unroll
                for (int ni = 0; ni < NT; ++ni)
                    mma16(acc[mi][ni], fa0.x, fa1.x, fa0.y, fa1.y,
                          fb[ni].x, fb[ni].y);
            }
        }
    }

    // epilogue
    float* Df = reinterpret_cast<float*>(Dv)
              + (SPLITK ? (size_t)blockIdx.z * NTOK * N : 0);
    __half* Dh = reinterpret_cast<__half*>(Dv);
    #pragma unroll
    for (int mi = 0; mi < MT; ++mi) {
        const int r0 = bM + wm + mi * 16 + gid;
        #pragma unroll
        for (int ni = 0; ni < NT; ++ni) {
            const int cl = wn + ni * 8 + tig * 2;
            const int c  = bN + cl;
            const float bb0 = HAS_BIAS ? bias[c] : 0.f;
            const float bb1 = HAS_BIAS ? bias[c + 1] : 0.f;
            #pragma unroll
            for (int h = 0; h < 2; ++h) {
                const int r = r0 + h * 8;
                float v0 = acc[mi][ni][2 * h + 0] + bb0;
                float v1 = acc[mi][ni][2 * h + 1] + bb1;
                if (EPI == 1) { v0 = fmaxf(v0, 0.f); v1 = fmaxf(v1, 0.f); }
                if (OUTH) {
                    const int pos = (c & ~15) + ipos16(c & 15);
                    *reinterpret_cast<__half2*>(Dh + (size_t)r * N + pos) =
                        __floats2half2_rn(v0, v1);
                } else {
                    *reinterpret_cast<float2*>(Df + (size_t)r * N + c) = make_float2(v0, v1);
                }
            }
        }
    }
}

// ---------------------------------------------------------------------------
extern "C" void kernel_launch(void* const* d_in, const int* in_sizes, int n_in,
                              void* d_out, int out_size) {
    const float* x       = (const float*)d_in[0];
    const float* gate_w1 = (const float*)d_in[1];
    const float* gate_b1 = (const float*)d_in[2];
    const float* gate_w2 = (const float*)d_in[3];
    const float* gate_b2 = (const float*)d_in[4];
    const float* W1      = (const float*)d_in[5];
    const float* b1      = (const float*)d_in[6];
    const float* W2      = (const float*)d_in[7];
    const float* b2      = (const float*)d_in[8];
    const float* U1      = (const float*)d_in[9];
    const float* SVH1    = (const float*)d_in[10];
    const float* U2      = (const float*)d_in[11];
    const float* SVH2    = (const float*)d_in[12];
    const float* TB1     = (const float*)d_in[13];
    const float* TB2     = (const float*)d_in[14];
    float* out = (float*)d_out;

    float* S = nullptr;
    cudaGetSymbolAddress((void**)&S, g_scratch);
    __half* xc    = (__half*)(S + OFF_XC);
    __half* wg1c  = (__half*)(S + OFF_WG1);
    __half* svh1c = (__half*)(S + OFF_SVH1);
    __half* w1c   = (__half*)(S + OFF_W1);
    __half* u1t   = (__half*)(S + OFF_U1T);
    __half* svh2c = (__half*)(S + OFF_SVH2);
    __half* w2c   = (__half*)(S + OFF_W2);
    __half* u2t   = (__half*)(S + OFF_U2T);
    __half* t1s   = (__half*)(S + OFF_T1S);
    __half* t2s   = (__half*)(S + OFF_T2S);
    __half* hbuf  = (__half*)(S + OFF_H);
    float* G1    = S + OFF_G1;
    float* t2p   = S + OFF_T2P;
    float* t1p   = S + OFF_T1P;
    float* P8    = S + OFF_P8;
    float* gwv   = S + OFF_GWV;
    float* b1m   = S + OFF_B1M;
    float* b2m   = S + OFF_B2M;

    // router: BM64 BN128, 8 warps (2x4), warp 32x32, 4 stages, fp32 out
    auto kr = k_mma<64, 128, 2, 4, 4, 1, false, true, false, false>;
    // t partial GEMMs: BM64 BN128, split-K, fp32 raw partials, 4 stages
    auto kt = k_mma<64, 128, 2, 4, 4, 0, false, false, false, true>;
    // fc1: BM128 BN128, 8 warps (2x4), warp 64x32, 4 stages, fp16 ILV out
    auto k1 = k_mma<128, 128, 2, 4, 4, 1, true, true, true, false>;
    // fc2: same, fp32 out
    auto k2 = k_mma<128, 128, 2, 4, 4, 0, true, true, false, false>;

    const int SM_RT = 4 * (64 + 128) * 96;     // 73728
    const int SM_F  = 4 * (128 + 128) * 96;    // 98304
    cudaFuncSetAttribute((const void*)kr, cudaFuncAttributeMaxDynamicSharedMemorySize, SM_RT);
    cudaFuncSetAttribute((const void*)kt, cudaFuncAttributeMaxDynamicSharedMemorySize, SM_RT);
    cudaFuncSetAttribute((const void*)k1, cudaFuncAttributeMaxDynamicSharedMemorySize, SM_F);
    cudaFuncSetAttribute((const void*)k2, cudaFuncAttributeMaxDynamicSharedMemorySize, SM_F);

    // 0: all fp32->fp16(rn) packs with k-permutation, one launch
    PackJobs J;
    J.src[0] = x;       J.dst[0] = (float*)xc;    J.ngroups[0] = NTOK * HQ / 16;
    J.src[1] = gate_w1; J.dst[1] = (float*)wg1c;  J.ngroups[1] = G1Q * HQ / 16;
    J.src[2] = SVH1;    J.dst[2] = (float*)svh1c; J.ngroups[2] = EKQ * HQ / 16;
    J.src[3] = W1;      J.dst[3] = (float*)w1c;   J.ngroups[3] = FQ * HQ / 16;
    J.src[4] = SVH2;    J.dst[4] = (float*)svh2c; J.ngroups[4] = EKQ * FQ / 16;
    J.src[5] = W2;      J.dst[5] = (float*)w2c;   J.ngroups[5] = HQ * FQ / 16;
    k_pack6<<<dim3((NTOK * HQ / 16 + 255) / 256, 6), 256>>>(J);

    // 1: router G1 = relu(x @ gate_w1^T + gate_b1)   [8192,256] fp32
    kr<<<dim3(G1Q / 128, NTOK / 64), 256, SM_RT>>>(
        xc, wg1c, HQ, nullptr, nullptr, 0, gate_b1, G1, G1Q, 0);

    // 2: partial sums over S
    k_sumG1b<<<dim3(BQ, 8), 256>>>(G1, P8);

    // 3: t1 partials = x @ SVH1^T, K split 2x384   << profiled slot
    kt<<<dim3(1, NTOK / 64, 2), 256, SM_RT>>>(
        xc, svh1c, HQ, nullptr, nullptr, 0, nullptr, t1p, EKQ, HQ / 2);

    // 4: gw
    k_gwfin<<<BQ, 128>>>(P8, gate_w2, gate_b2, gwv);

    // 5: t1s = fp16(sum_z t1p * gw), permuted
    k_red<2><<<NTOK * 64 / 256, 256>>>(t1p, gwv, t1s);

    // 6,7: transposed low-rank factors -> fp16 permuted
    k_tr_ilv<<<dim3(FQ / 32, 4), dim3(32, 8)>>>(U1, u1t, FQ);
    k_tr_ilv<<<dim3(HQ / 32, 4), dim3(32, 8)>>>(U2, u2t, HQ);

    // 8: merged biases (fp32)
    k_prep<<<(FQ + 255) / 256, 256>>>(b1, TB1, b2, TB2, b1m, b2m);

    // 9: h = fp16(relu(x @ W1^T + t1s @ U1 + b1m))   [8192,3072]
    k1<<<dim3(FQ / 128, NTOK / 128), 256, SM_F>>>(
        xc, w1c, HQ, t1s, u1t, EKQ, b1m, hbuf, FQ, 0);

    // 10: t2 partials = h @ SVH2^T, K split 4x768
    kt<<<dim3(1, NTOK / 64, 4), 256, SM_RT>>>(
        hbuf, svh2c, FQ, nullptr, nullptr, 0, nullptr, t2p, EKQ, FQ / 4);

    // 11: t2s = fp16(sum_z t2p * gw), permuted
    k_red<4><<<NTOK * 64 / 256, 256>>>(t2p, gwv, t2s);

    // 12: out = h @ W2^T + t2s @ U2 + b2m   [8192,768] fp32
    k2<<<dim3(HQ / 128, NTOK / 128), 256, SM_F>>>(
        hbuf, w2c, FQ, t2s, u2t, EKQ, b2m, out, HQ, 0);
}

// round 9
// speedup vs baseline: 1.9243x; 1.0330x over previous
#include <cuda_runtime.h>
#include <cuda_fp16.h>
#include <cstdint>
#include <cstddef>

// ---------------------------------------------------------------------------
// RankOneMoE via fp16 mma.sync.m16n8k16 (fp32 accumulate). fp16 mantissa ==
// tf32 mantissa, so rn-rounded fp16 operands give tf32-grade accuracy at half
// the MMA instructions and half the smem bytes.
//   gw[b,ek]  = (sum_s relu(x@gw1^T+b1g))[b,:]@gw2[ek,:]^T /512 + b2g[ek]
//   h         = relu([x | (x@SVH1^T)*gw] @ [W1^T ; U1] + b1m)
//   out       = [h | (h@SVH2^T)*gw] @ [W2^T ; U2] + b2m
// Per-16 k-pair permutation [0,1,8,9,2,3,10,11,...] -> fragment = 1 LDS.64.
// Rows padded to 96B (conflict-free LDS.64).
// R9: fc warp tiles widened to 64x64 (MT4 NT8) -> smem bytes/MMA cut 33%;
//     4 warps/CTA, 2 CTA/SM via launch_bounds(128,2).
// ---------------------------------------------------------------------------

#define BQ   16
#define SQ   512
#define HQ   768
#define FQ   3072
#define EQ   8
#define EKQ  128
#define G1Q  256
#define NTOK (BQ*SQ)      // 8192
#define LAMBDA 0.2f

// ---- scratch layout (float units; fp16 buffers use half the floats) ----
#define OFF_XC    0                         // 8192*768 h
#define OFF_WG1   3145728                   // 256*768 h
#define OFF_SVH1  3244032                   // 128*768 h
#define OFF_W1    3293184                   // 3072*768 h
#define OFF_U1T   4472832                   // 3072*128 h
#define OFF_SVH2  4669440                   // 128*3072 h
#define OFF_W2    4866048                   // 768*3072 h
#define OFF_U2T   6045696                   // 768*128 h
#define OFF_G1    6094848                   // 8192*256 f
#define OFF_T1S   8192000                   // 8192*128 h
#define OFF_T2S   8716288                   // 8192*128 h
#define OFF_H     9240576                   // 8192*3072 h
#define OFF_T2P   21823488                  // 4*8192*128 f
#define OFF_P8    26017792                  // 16*8*256 f
#define OFF_GWV   26050560                  // 16*128 f
#define OFF_B1M   26052608                  // 3072 f
#define OFF_B2M   26055680                  // 768 f
#define OFF_T1P   26056448                  // 2*8192*128 f
#define SCRATCH_FLOATS 28153600

static __device__ __align__(256) float g_scratch[SCRATCH_FLOATS];

// ---------------------------- helpers --------------------------------------
__device__ __forceinline__ uint32_t s2u(const void* p) {
    uint32_t a;
    asm("{ .reg .u64 t; cvta.to.shared.u64 t, %1; cvt.u32.u64 %0, t; }" : "=r"(a) : "l"(p));
    return a;
}
// position of original k (0..15) inside the permuted 16-group
__device__ __forceinline__ int ipos16(int k) {
    return (k & 1) + ((k >> 3) & 1) * 2 + (k & 6) * 2;
}
__device__ __forceinline__ void mma16(float* c,
                                      uint32_t a0, uint32_t a1, uint32_t a2, uint32_t a3,
                                      uint32_t b0, uint32_t b1) {
    asm volatile(
        "mma.sync.aligned.m16n8k16.row.col.f32.f16.f16.f32 "
        "{%0,%1,%2,%3},{%4,%5,%6,%7},{%8,%9},{%0,%1,%2,%3};\n"
        : "+f"(c[0]), "+f"(c[1]), "+f"(c[2]), "+f"(c[3])
        : "r"(a0), "r"(a1), "r"(a2), "r"(a3), "r"(b0), "r"(b1));
}

// ---------------------------- pack kernels ---------------------------------
struct PackJobs {
    const float* src[6];
    float*       dst[6];   // fp16 storage viewed as float words
    int          ngroups[6];
};

// fp32 -> fp16(rn) with per-16 k-pair permutation [0,1,8,9,2,3,10,11,...]
__global__ void k_pack6(PackJobs J) {
    const int job = blockIdx.y;
    const int g = blockIdx.x * blockDim.x + threadIdx.x;
    if (g >= J.ngroups[job]) return;
    const float4* s = reinterpret_cast<const float4*>(J.src[job]) + (size_t)g * 4;
    float4 v0 = s[0], v1 = s[1], v2 = s[2], v3 = s[3];   // k0-3, k4-7, k8-11, k12-15
    __half2 h[8];
    h[0] = __floats2half2_rn(v0.x, v0.y);   // k0,1
    h[1] = __floats2half2_rn(v2.x, v2.y);   // k8,9
    h[2] = __floats2half2_rn(v0.z, v0.w);   // k2,3
    h[3] = __floats2half2_rn(v2.z, v2.w);   // k10,11
    h[4] = __floats2half2_rn(v1.x, v1.y);   // k4,5
    h[5] = __floats2half2_rn(v3.x, v3.y);   // k12,13
    h[6] = __floats2half2_rn(v1.z, v1.w);   // k6,7
    h[7] = __floats2half2_rn(v3.z, v3.w);   // k14,15
    float4* d = reinterpret_cast<float4*>(reinterpret_cast<__half*>(J.dst[job]) + (size_t)g * 16);
    d[0] = *reinterpret_cast<float4*>(&h[0]);
    d[1] = *reinterpret_cast<float4*>(&h[4]);
}

// transpose src[128, Ncols] f32 -> dst[Ncols, 128] fp16 permuted
__global__ void k_tr_ilv(const float* __restrict__ S_, __half* __restrict__ Dst, int Ncols) {
    __shared__ float t[32][33];
    const int nx = blockIdx.x * 32, my = blockIdx.y * 32;
    const int x = threadIdx.x, y = threadIdx.y;
    #pragma unroll
    for (int i = 0; i < 32; i += 8)
        t[y + i][x] = S_[(size_t)(my + y + i) * Ncols + nx + x];
    __syncthreads();
    #pragma unroll
    for (int i = 0; i < 32; i += 8) {
        const int r = my + x;                 // original row (k of U^T)
        const int pos = (r & ~15) + ipos16(r & 15);
        Dst[(size_t)(nx + y + i) * 128 + pos] = __float2half_rn(t[x][y + i]);
    }
}

__global__ void k_prep(const float* __restrict__ b1, const float* __restrict__ tb1,
                       const float* __restrict__ b2, const float* __restrict__ tb2,
                       float* __restrict__ b1m, float* __restrict__ b2m) {
    int i = blockIdx.x * blockDim.x + threadIdx.x;
    if (i < FQ) {
        float s = 0.f;
        #pragma unroll
        for (int e = 0; e < EQ; ++e) s += tb1[e * FQ + i];
        b1m[i] = b1[i] + LAMBDA * s;
    }
    if (i < HQ) {
        float s = 0.f;
        #pragma unroll
        for (int e = 0; e < EQ; ++e) s += tb2[e * HQ + i];
        b2m[i] = b2[i] + LAMBDA * s;
    }
}

// two-level mean reduction over S (level 1)
__global__ void k_sumG1b(const float* __restrict__ G1, float* __restrict__ P8) {
    int b = blockIdx.x, ch = blockIdx.y, g = threadIdx.x;      // 256 threads
    const float* p = G1 + ((size_t)b * SQ + ch * 64) * G1Q + g;
    float a = 0.f;
    #pragma unroll 8
    for (int s = 0; s < 64; ++s) a += p[(size_t)s * G1Q];
    P8[(b * 8 + ch) * G1Q + g] = a;
}

// gw[b,ek] = dot(P[b,:], w2[ek,:]) / 512 + gb2[ek]
__global__ void k_gwfin(const float* __restrict__ P8, const float* __restrict__ w2,
                        const float* __restrict__ gb2, float* __restrict__ gw) {
    __shared__ float Ps[G1Q];
    int b = blockIdx.x, t = threadIdx.x;   // 128 threads
    #pragma unroll
    for (int half = 0; half < 2; ++half) {
        int col = t + half * 128;
        float a = 0.f;
        #pragma unroll
        for (int ch = 0; ch < 8; ++ch) a += P8[(b * 8 + ch) * G1Q + col];
        Ps[col] = a;
    }
    __syncthreads();
    const float* w = w2 + (size_t)t * G1Q;
    float a = 0.f;
    #pragma unroll 8
    for (int g = 0; g < G1Q; ++g) a += w[g] * Ps[g];
    gw[b * EKQ + t] = a * (1.0f / (float)SQ) + gb2[t];
}

// split-K reduce: sum KS partials, scale by gw, convert to fp16 permuted
template<int KS>
__global__ void k_red(const float* __restrict__ tp, const float* __restrict__ gwv,
                      __half* __restrict__ ts) {
    const int idx = blockIdx.x * 256 + threadIdx.x;   // over NTOK*64 pairs
    const int r = idx >> 6, c = (idx & 63) * 2;
    float v0 = tp[(size_t)r * EKQ + c];
    float v1 = tp[(size_t)r * EKQ + c + 1];
    #pragma unroll
    for (int z = 1; z < KS; ++z) {
        v0 += tp[(size_t)z * NTOK * EKQ + (size_t)r * EKQ + c];
        v1 += tp[(size_t)z * NTOK * EKQ + (size_t)r * EKQ + c + 1];
    }
    const int gb = (r >> 9) << 7;
    v0 *= gwv[gb + c]; v1 *= gwv[gb + c + 1];
    const int pos = (c & ~15) + ipos16(c & 15);       // pairs stay adjacent
    *reinterpret_cast<__half2*>(ts + (size_t)r * EKQ + pos) = __floats2half2_rn(v0, v1);
}

// ---------------------------------------------------------------------------
// Pipelined fp16 mma.sync GEMM. BK=32 per stage (two 16-k groups), STAGES-deep
// cp.async. Smem rows: 32 halfs data (64B), stride 96B (conflict-free LDS.64).
//   D = epi( A1[M,K1] @ B1[N,K1]^T (+ A2[M,K2] @ B2[N,K2]^T) )
//   EPI: 0=none, 1=relu. OUTH: fp16 permuted output.
//   SPLITK: blockIdx.z picks a kspan window of K1; D offset by z*NTOK*N.
// ---------------------------------------------------------------------------
template<int BM, int BN, int WM, int WN, int STAGES, int EPI,
         bool HAS2, bool HAS_BIAS, bool OUTH, bool SPLITK>
__global__ void __launch_bounds__(WM * WN * 32, 2)
k_mma(const __half* __restrict__ A1, const __half* __restrict__ B1, int K1,
      const __half* __restrict__ A2, const __half* __restrict__ B2, int K2,
      const float* __restrict__ bias,
      void* __restrict__ Dv, int N, int kspan)
{
    constexpr int THREADS = WM * WN * 32;
    constexpr int WTM = BM / WM, WTN = BN / WN;
    constexpr int MT = WTM / 16, NT = WTN / 8;
    constexpr int RB = 96;                        // padded row bytes (64B data)
    constexpr int STGB = (BM + BN) * RB;          // stage bytes
    constexpr int AIT = (BM * 4) / THREADS;       // 16B chunks per thread (A)
    constexpr int BIT = (BN * 4) / THREADS;

    extern __shared__ char sm[];
    const uint32_t smb = s2u(sm);

    const int tid = threadIdx.x;
    const int wid = tid >> 5, lane = tid & 31;
    const int gid = lane >> 2, tig = lane & 3;
    const int wm = (wid / WN) * WTM;
    const int wn = (wid % WN) * WTN;
    const int bM = blockIdx.y * BM;
    const int bN = blockIdx.x * BN;
    const int kbase = SPLITK ? blockIdx.z * kspan : 0;
    const int T1S = SPLITK ? (kspan >> 5) : (K1 >> 5);
    const int TS  = T1S + (HAS2 ? (K2 >> 5) : 0);

    float acc[MT][NT][4];
    #pragma unroll
    for (int mi = 0; mi < MT; ++mi)
        #pragma unroll
        for (int ni = 0; ni < NT; ++ni)
            #pragma unroll
            for (int j = 0; j < 4; ++j) acc[mi][ni][j] = 0.f;

    auto issue = [&](int jj) {
        const __half* a; const __half* b; int lda, ldb, k0;
        if (!HAS2 || jj < T1S) { a = A1; lda = K1; b = B1; ldb = K1; k0 = kbase + (jj << 5); }
        else                   { a = A2; lda = K2; b = B2; ldb = K2; k0 = (jj - T1S) << 5; }
        const uint32_t sA = smb + (uint32_t)((jj % STAGES) * STGB);
        const uint32_t sB = sA + (uint32_t)BM * RB;
        #pragma unroll
        for (int i = 0; i < AIT; ++i) {
            int idx = tid + i * THREADS; int r = idx >> 2, c = idx & 3;
            const __half* src = a + (size_t)(bM + r) * lda + k0 + c * 8;
            asm volatile("cp.async.cg.shared.global [%0], [%1], 16;\n"
                         :: "r"(sA + (uint32_t)(r * RB + c * 16)), "l"(src) : "memory");
        }
        #pragma unroll
        for (int i = 0; i < BIT; ++i) {
            int idx = tid + i * THREADS; int r = idx >> 2, c = idx & 3;
            const __half* src = b + (size_t)(bN + r) * ldb + k0 + c * 8;
            asm volatile("cp.async.cg.shared.global [%0], [%1], 16;\n"
                         :: "r"(sB + (uint32_t)(r * RB + c * 16)), "l"(src) : "memory");
        }
    };

    #pragma unroll
    for (int s = 0; s < STAGES - 1; ++s) {
        issue(s);
        asm volatile("cp.async.commit_group;\n" ::: "memory");
    }

    for (int j = 0; j < TS; ++j) {
        asm volatile("cp.async.wait_group %0;\n" :: "n"(STAGES - 2) : "memory");
        __syncthreads();

        const char* sst = sm + (j % STAGES) * STGB;
        const char* sA = sst;
        const char* sB = sst + BM * RB;

        #pragma unroll
        for (int g = 0; g < 2; ++g) {
            uint2 fb[NT];
            #pragma unroll
            for (int ni = 0; ni < NT; ++ni)
                fb[ni] = *reinterpret_cast<const uint2*>(
                    sB + (wn + ni * 8 + gid) * RB + g * 32 + tig * 8);

            if (g == 0) {
                if (j + STAGES - 1 < TS) issue(j + STAGES - 1);
                asm volatile("cp.async.commit_group;\n" ::: "memory");
            }

            #pragma unroll
            for (int mi = 0; mi < MT; ++mi) {
                const char* ra = sA + (wm + mi * 16 + gid) * RB + g * 32 + tig * 8;
                const uint2 fa0 = *reinterpret_cast<const uint2*>(ra);
                const uint2 fa1 = *reinterpret_cast<const uint2*>(ra + 8 * RB);
                #pragma unroll
                for (int ni = 0; ni < NT; ++ni)
                    mma16(acc[mi][ni], fa0.x, fa1.x, fa0.y, fa1.y,
                          fb[ni].x, fb[ni].y);
            }
        }
    }

    // epilogue
    float* Df = reinterpret_cast<float*>(Dv)
              + (SPLITK ? (size_t)blockIdx.z * NTOK * N : 0);
    __half* Dh = reinterpret_cast<__half*>(Dv);
    #pragma unroll
    for (int mi = 0; mi < MT; ++mi) {
        const int r0 = bM + wm + mi * 16 + gid;
        #pragma unroll
        for (int ni = 0; ni < NT; ++ni) {
            const int cl = wn + ni * 8 + tig * 2;
            const int c  = bN + cl;
            const float bb0 = HAS_BIAS ? bias[c] : 0.f;
            const float bb1 = HAS_BIAS ? bias[c + 1] : 0.f;
            #pragma unroll
            for (int h = 0; h < 2; ++h) {
                const int r = r0 + h * 8;
                float v0 = acc[mi][ni][2 * h + 0] + bb0;
                float v1 = acc[mi][ni][2 * h + 1] + bb1;
                if (EPI == 1) { v0 = fmaxf(v0, 0.f); v1 = fmaxf(v1, 0.f); }
                if (OUTH) {
                    const int pos = (c & ~15) + ipos16(c & 15);
                    *reinterpret_cast<__half2*>(Dh + (size_t)r * N + pos) =
                        __floats2half2_rn(v0, v1);
                } else {
                    *reinterpret_cast<float2*>(Df + (size_t)r * N + c) = make_float2(v0, v1);
                }
            }
        }
    }
}

// ---------------------------------------------------------------------------
extern "C" void kernel_launch(void* const* d_in, const int* in_sizes, int n_in,
                              void* d_out, int out_size) {
    const float* x       = (const float*)d_in[0];
    const float* gate_w1 = (const float*)d_in[1];
    const float* gate_b1 = (const float*)d_in[2];
    const float* gate_w2 = (const float*)d_in[3];
    const float* gate_b2 = (const float*)d_in[4];
    const float* W1      = (const float*)d_in[5];
    const float* b1      = (const float*)d_in[6];
    const float* W2      = (const float*)d_in[7];
    const float* b2      = (const float*)d_in[8];
    const float* U1      = (const float*)d_in[9];
    const float* SVH1    = (const float*)d_in[10];
    const float* U2      = (const float*)d_in[11];
    const float* SVH2    = (const float*)d_in[12];
    const float* TB1     = (const float*)d_in[13];
    const float* TB2     = (const float*)d_in[14];
    float* out = (float*)d_out;

    float* S = nullptr;
    cudaGetSymbolAddress((void**)&S, g_scratch);
    __half* xc    = (__half*)(S + OFF_XC);
    __half* wg1c  = (__half*)(S + OFF_WG1);
    __half* svh1c = (__half*)(S + OFF_SVH1);
    __half* w1c   = (__half*)(S + OFF_W1);
    __half* u1t   = (__half*)(S + OFF_U1T);
    __half* svh2c = (__half*)(S + OFF_SVH2);
    __half* w2c   = (__half*)(S + OFF_W2);
    __half* u2t   = (__half*)(S + OFF_U2T);
    __half* t1s   = (__half*)(S + OFF_T1S);
    __half* t2s   = (__half*)(S + OFF_T2S);
    __half* hbuf  = (__half*)(S + OFF_H);
    float* G1    = S + OFF_G1;
    float* t2p   = S + OFF_T2P;
    float* t1p   = S + OFF_T1P;
    float* P8    = S + OFF_P8;
    float* gwv   = S + OFF_GWV;
    float* b1m   = S + OFF_B1M;
    float* b2m   = S + OFF_B2M;

    // router: BM64 BN128, 8 warps (2x4), warp 32x32, 4 stages, fp32 out
    auto kr = k_mma<64, 128, 2, 4, 4, 1, false, true, false, false>;
    // t partial GEMMs: BM64 BN128, split-K, fp32 raw partials, 4 stages
    auto kt = k_mma<64, 128, 2, 4, 4, 0, false, false, false, true>;
    // fc1: BM128 BN128, 4 warps (2x2), warp 64x64 (MT4 NT8), 4 stages
    auto k1 = k_mma<128, 128, 2, 2, 4, 1, true, true, true, false>;
    // fc2: same shape, fp32 out
    auto k2 = k_mma<128, 128, 2, 2, 4, 0, true, true, false, false>;

    const int SM_RT = 4 * (64 + 128) * 96;     // 73728
    const int SM_F  = 4 * (128 + 128) * 96;    // 98304
    cudaFuncSetAttribute((const void*)kr, cudaFuncAttributeMaxDynamicSharedMemorySize, SM_RT);
    cudaFuncSetAttribute((const void*)kt, cudaFuncAttributeMaxDynamicSharedMemorySize, SM_RT);
    cudaFuncSetAttribute((const void*)k1, cudaFuncAttributeMaxDynamicSharedMemorySize, SM_F);
    cudaFuncSetAttribute((const void*)k2, cudaFuncAttributeMaxDynamicSharedMemorySize, SM_F);

    // 0: all fp32->fp16(rn) packs with k-permutation, one launch
    PackJobs J;
    J.src[0] = x;       J.dst[0] = (float*)xc;    J.ngroups[0] = NTOK * HQ / 16;
    J.src[1] = gate_w1; J.dst[1] = (float*)wg1c;  J.ngroups[1] = G1Q * HQ / 16;
    J.src[2] = SVH1;    J.dst[2] = (float*)svh1c; J.ngroups[2] = EKQ * HQ / 16;
    J.src[3] = W1;      J.dst[3] = (float*)w1c;   J.ngroups[3] = FQ * HQ / 16;
    J.src[4] = SVH2;    J.dst[4] = (float*)svh2c; J.ngroups[4] = EKQ * FQ / 16;
    J.src[5] = W2;      J.dst[5] = (float*)w2c;   J.ngroups[5] = HQ * FQ / 16;
    k_pack6<<<dim3((NTOK * HQ / 16 + 255) / 256, 6), 256>>>(J);

    // 1: router G1 = relu(x @ gate_w1^T + gate_b1)   [8192,256] fp32
    kr<<<dim3(G1Q / 128, NTOK / 64), 256, SM_RT>>>(
        xc, wg1c, HQ, nullptr, nullptr, 0, gate_b1, G1, G1Q, 0);

    // 2: partial sums over S
    k_sumG1b<<<dim3(BQ, 8), 256>>>(G1, P8);

    // 3: t1 partials = x @ SVH1^T, K split 2x384   << profiled slot
    kt<<<dim3(1, NTOK / 64, 2), 256, SM_RT>>>(
        xc, svh1c, HQ, nullptr, nullptr, 0, nullptr, t1p, EKQ, HQ / 2);

    // 4: gw
    k_gwfin<<<BQ, 128>>>(P8, gate_w2, gate_b2, gwv);

    // 5: t1s = fp16(sum_z t1p * gw), permuted
    k_red<2><<<NTOK * 64 / 256, 256>>>(t1p, gwv, t1s);

    // 6,7: transposed low-rank factors -> fp16 permuted
    k_tr_ilv<<<dim3(FQ / 32, 4), dim3(32, 8)>>>(U1, u1t, FQ);
    k_tr_ilv<<<dim3(HQ / 32, 4), dim3(32, 8)>>>(U2, u2t, HQ);

    // 8: merged biases (fp32)
    k_prep<<<(FQ + 255) / 256, 256>>>(b1, TB1, b2, TB2, b1m, b2m);

    // 9: h = fp16(relu(x @ W1^T + t1s @ U1 + b1m))   [8192,3072]
    k1<<<dim3(FQ / 128, NTOK / 128), 128, SM_F>>>(
        xc, w1c, HQ, t1s, u1t, EKQ, b1m, hbuf, FQ, 0);

    // 10: t2 partials = h @ SVH2^T, K split 4x768
    kt<<<dim3(1, NTOK / 64, 4), 256, SM_RT>>>(
        hbuf, svh2c, FQ, nullptr, nullptr, 0, nullptr, t2p, EKQ, FQ / 4);

    // 11: t2s = fp16(sum_z t2p * gw), permuted
    k_red<4><<<NTOK * 64 / 256, 256>>>(t2p, gwv, t2s);

    // 12: out = h @ W2^T + t2s @ U2 + b2m   [8192,768] fp32
    k2<<<dim3(HQ / 128, NTOK / 128), 128, SM_F>>>(
        hbuf, w2c, FQ, t2s, u2t, EKQ, b2m, out, HQ, 0);
}